// round 2
// baseline (speedup 1.0000x reference)
#include <cuda_runtime.h>

// Problem constants
#define B_ 8192
#define T_ 336
#define F_ 8
#define H_ 20
#define G_ 80   // 4*H gates

// Inter-layer hidden-sequence scratch (allowed: __device__ globals)
__device__ float g_buf0[(size_t)B_ * T_ * H_];
__device__ float g_buf1[(size_t)B_ * T_ * H_];

__device__ __forceinline__ float fsig(float x) {
    return __fdividef(1.f, 1.f + __expf(-x));
}
__device__ __forceinline__ float ftanh(float x) {
    return __fdividef(2.f, 1.f + __expf(-2.f * x)) - 1.f;
}

// SRC: 0 = param in_seq, 1 = g_buf0, 2 = g_buf1
// DST: 0 = g_buf0, 1 = g_buf1, 2 = final (FC head -> out_final)
template <int IN, int SRC, int DST>
__global__ __launch_bounds__(256)
void lstm_layer_kernel(
    const float* __restrict__ in_seq,
    const float* __restrict__ W_ih,   // [80, IN]
    const float* __restrict__ W_hh,   // [80, 20]
    const float* __restrict__ b_ih,   // [80]
    const float* __restrict__ b_hh,   // [80]
    const float* __restrict__ fc1_w,  // [20, 20]
    const float* __restrict__ fc1_b,  // [20]
    const float* __restrict__ fc2_w,  // [20]
    const float* __restrict__ fc2_b,  // [1]
    float* __restrict__ out_final)    // [B]
{
    constexpr int KTOT = IN + H_;
    constexpr bool FINAL = (DST == 2);

    // Weights staged gate-major: sW[k*80 + g], so lanes (g = lane) read
    // consecutive addresses -> conflict-free LDS.
    __shared__ float sW[KTOT * G_];
    __shared__ float sB[G_];
    __shared__ float sFC[H_ * H_ + H_ + H_ + 1]; // fc1_w | fc1_b | fc2_w | fc2_b

    const int tid = threadIdx.x;
    for (int i = tid; i < KTOT * G_; i += blockDim.x) {
        int k = i / G_;
        int g = i - k * G_;
        sW[i] = (k < IN) ? W_ih[g * IN + k] : W_hh[g * H_ + (k - IN)];
    }
    if (tid < G_) sB[tid] = b_ih[tid] + b_hh[tid];
    if (FINAL) {
        for (int i = tid; i < H_ * H_; i += blockDim.x) sFC[i] = fc1_w[i];
        if (tid < H_) {
            sFC[H_ * H_ + tid]      = fc1_b[tid];
            sFC[H_ * H_ + H_ + tid] = fc2_w[tid];
        }
        if (tid == 0) sFC[H_ * H_ + 2 * H_] = fc2_b[0];
    }
    __syncthreads();

    const int warp = tid >> 5;
    const int lane = tid & 31;
    const int elem = blockIdx.x * (blockDim.x >> 5) + warp;
    if (elem >= B_) return;

    const int jj = (lane < H_) ? lane : 0;  // lanes >= 20 shadow lane 0 (results unused)
    const float bi = sB[jj];
    const float bf = sB[jj + 20];
    const float bg = sB[jj + 40];
    const float bo = sB[jj + 60];

    const float* __restrict__ src =
        (SRC == 0) ? in_seq : ((SRC == 1) ? (const float*)g_buf0 : (const float*)g_buf1);
    float* __restrict__ dst = (DST == 0) ? g_buf0 : g_buf1;

    const float* __restrict__ inp = src + (size_t)elem * T_ * IN;
    float* __restrict__ outp = FINAL ? nullptr : dst + (size_t)elem * T_ * H_;

    float h = 0.f, c = 0.f;

    for (int t = 0; t < T_; ++t) {
        float xv = 0.f;
        if (lane < IN) xv = inp[t * IN + lane];

        float a0 = bi, a1 = bf, a2 = bg, a3 = bo;

        #pragma unroll
        for (int k = 0; k < IN; ++k) {
            float v = __shfl_sync(0xFFFFFFFFu, xv, k);
            const float* w = &sW[k * G_ + jj];
            a0 = fmaf(v, w[0],  a0);
            a1 = fmaf(v, w[20], a1);
            a2 = fmaf(v, w[40], a2);
            a3 = fmaf(v, w[60], a3);
        }
        #pragma unroll
        for (int k = 0; k < H_; ++k) {
            float v = __shfl_sync(0xFFFFFFFFu, h, k);
            const float* w = &sW[(IN + k) * G_ + jj];
            a0 = fmaf(v, w[0],  a0);
            a1 = fmaf(v, w[20], a1);
            a2 = fmaf(v, w[40], a2);
            a3 = fmaf(v, w[60], a3);
        }

        float ig = fsig(a0);
        float fg = fsig(a1);
        float gg = ftanh(a2);
        float og = fsig(a3);
        c = fmaf(fg, c, ig * gg);
        h = og * ftanh(c);

        if (!FINAL && lane < H_) outp[t * H_ + lane] = h;
    }

    if (FINAL) {
        // fc1: dense_j = relu(sum_k h_k * fc1_w[j,k] + fc1_b[j])
        float d = sFC[H_ * H_ + jj];
        #pragma unroll
        for (int k = 0; k < H_; ++k) {
            float v = __shfl_sync(0xFFFFFFFFu, h, k);
            d = fmaf(v, sFC[jj * H_ + k], d);
        }
        d = fmaxf(d, 0.f);
        // fc2: scalar output = sum_j dense_j * fc2_w[j] + fc2_b
        float p = (lane < H_) ? d * sFC[H_ * H_ + H_ + lane] : 0.f;
        #pragma unroll
        for (int o = 16; o > 0; o >>= 1)
            p += __shfl_xor_sync(0xFFFFFFFFu, p, o);
        if (lane == 0) out_final[elem] = p + sFC[H_ * H_ + 2 * H_];
    }
}

extern "C" void kernel_launch(void* const* d_in, const int* in_sizes, int n_in,
                              void* d_out, int out_size) {
    const float* x     = (const float*)d_in[0];
    const float* Wih0  = (const float*)d_in[1];
    const float* Whh0  = (const float*)d_in[2];
    const float* bih0  = (const float*)d_in[3];
    const float* bhh0  = (const float*)d_in[4];
    const float* Wih1  = (const float*)d_in[5];
    const float* Whh1  = (const float*)d_in[6];
    const float* bih1  = (const float*)d_in[7];
    const float* bhh1  = (const float*)d_in[8];
    const float* Wih2  = (const float*)d_in[9];
    const float* Whh2  = (const float*)d_in[10];
    const float* bih2  = (const float*)d_in[11];
    const float* bhh2  = (const float*)d_in[12];
    const float* fc1w  = (const float*)d_in[13];
    const float* fc1b  = (const float*)d_in[14];
    const float* fc2w  = (const float*)d_in[15];
    const float* fc2b  = (const float*)d_in[16];
    float* out = (float*)d_out;

    const int WARPS = 8;
    dim3 block(32 * WARPS);
    dim3 grid(B_ / WARPS);

    // Layer 0: x [B,T,8] -> g_buf0
    lstm_layer_kernel<F_, 0, 0><<<grid, block>>>(
        x, Wih0, Whh0, bih0, bhh0, nullptr, nullptr, nullptr, nullptr, nullptr);
    // Layer 1: g_buf0 -> g_buf1
    lstm_layer_kernel<H_, 1, 1><<<grid, block>>>(
        nullptr, Wih1, Whh1, bih1, bhh1, nullptr, nullptr, nullptr, nullptr, nullptr);
    // Layer 2 + FC head: g_buf1 -> out
    lstm_layer_kernel<H_, 2, 2><<<grid, block>>>(
        nullptr, Wih2, Whh2, bih2, bhh2, fc1w, fc1b, fc2w, fc2b, out);
}

// round 3
// speedup vs baseline: 1.4947x; 1.4947x over previous
#include <cuda_runtime.h>

// Problem constants
#define B_ 8192
#define T_ 336
#define F_ 8
#define H_ 20
#define G_ 80   // 4*H gate rows
#define EPB 4   // batch elements per block (block = EPB*80 = 320 threads)

// Inter-layer hidden-sequence scratch
__device__ float g_buf0[(size_t)B_ * T_ * H_];
__device__ float g_buf1[(size_t)B_ * T_ * H_];

// SRC: 0 = param in_seq, 1 = g_buf0, 2 = g_buf1
// DST: 0 = g_buf0, 1 = g_buf1, 2 = final (FC head -> out_final)
template <int IN, int SRC, int DST>
__global__ __launch_bounds__(32 * ((EPB * G_ + 31) / 32))
void lstm_fused(
    const float* __restrict__ in_seq,
    const float* __restrict__ W_ih,   // [80, IN]
    const float* __restrict__ W_hh,   // [80, 20]
    const float* __restrict__ b_ih,   // [80]
    const float* __restrict__ b_hh,   // [80]
    const float* __restrict__ fc1_w,  // [20, 20]
    const float* __restrict__ fc1_b,  // [20]
    const float* __restrict__ fc2_w,  // [20]
    const float* __restrict__ fc2_b,  // [1]
    float* __restrict__ out_final)    // [B]
{
    constexpr int KTOT = IN + H_;      // 28 or 40
    constexpr int K4   = KTOT / 4;     // 7 or 10 (both divide exactly)
    constexpr bool FINAL = (DST == 2);

    // Double-buffered [x_t | h] vector per element, float4-aligned.
    __shared__ float4 s_hx[2][EPB][K4];
    // Activated gate values per element.
    __shared__ float  s_g[EPB][G_];

    const int tid  = threadIdx.x;
    const int e    = tid / G_;         // 0..3
    const int g    = tid % G_;         // gate row 0..79
    const int unit = g % H_;           // hidden unit 0..19
    const int type = g / H_;           // 0=i 1=f 2=g 3=o
    const size_t elem = (size_t)blockIdx.x * EPB + e;

    // ---- weights & bias to registers (loop-invariant over 336 steps) ----
    float w[KTOT];
    #pragma unroll
    for (int k = 0; k < IN; ++k)  w[k]       = __ldg(&W_ih[g * IN + k]);
    #pragma unroll
    for (int k = 0; k < H_; ++k)  w[IN + k]  = __ldg(&W_hh[g * H_ + k]);
    const float bias = __ldg(&b_ih[g]) + __ldg(&b_hh[g]);

    const float* __restrict__ src =
        (SRC == 0) ? in_seq : ((SRC == 1) ? (const float*)g_buf0 : (const float*)g_buf1);
    float* __restrict__ dst = (DST == 0) ? g_buf0 : g_buf1;

    const float* __restrict__ inp  = src + elem * T_ * IN;
    float* __restrict__ outp = FINAL ? nullptr : dst + elem * T_ * H_;

    // ---- prologue: stage x_0 and h=0 into buffer 0 ----
    {
        float* hx0 = (float*)&s_hx[0][e][0];
        if (g < IN)               hx0[g] = inp[g];
        if (g >= 40 && g < 60)    hx0[IN + (g - 40)] = 0.f;
    }
    __syncthreads();

    float c = 0.f;   // cell state lives in the owner thread (type==0)
    int cur = 0;

    for (int t = 0; t < T_; ++t) {
        const float4* hx = &s_hx[cur][e][0];

        // gate pre-activation: KTOT FMAs, K4 float4 broadcast LDS
        float acc = bias;
        #pragma unroll
        for (int q = 0; q < K4; ++q) {
            float4 v = hx[q];
            acc = fmaf(v.x, w[4 * q + 0], acc);
            acc = fmaf(v.y, w[4 * q + 1], acc);
            acc = fmaf(v.z, w[4 * q + 2], acc);
            acc = fmaf(v.w, w[4 * q + 3], acc);
        }

        // activation: sigmoid for i/f/o, tanh for g (branchless)
        float vv = (type == 2) ? 2.f * acc : acc;
        float s  = __fdividef(1.f, 1.f + __expf(-vv));
        float act = (type == 2) ? fmaf(2.f, s, -1.f) : s;
        s_g[e][g] = act;

        // prefetch x_{t+1} into the next buffer (disjoint from current reads)
        float* hxn = (float*)&s_hx[cur ^ 1][e][0];
        if (g < IN && t + 1 < T_) hxn[g] = inp[(size_t)(t + 1) * IN + g];

        __syncthreads();

        if (type == 0) {
            float ig = s_g[e][unit];
            float fg = s_g[e][unit + 20];
            float gg = s_g[e][unit + 40];
            float og = s_g[e][unit + 60];
            c = fmaf(fg, c, ig * gg);
            float s2 = __fdividef(1.f, 1.f + __expf(-2.f * c));
            float h  = og * fmaf(2.f, s2, -1.f);
            hxn[IN + unit] = h;
            if (!FINAL) outp[(size_t)t * H_ + unit] = h;
        }

        __syncthreads();
        cur ^= 1;
    }

    if (FINAL) {
        // final h is in s_hx[cur][e] h-slots
        const float* hfin = (const float*)&s_hx[cur][e][0] + IN;
        if (type == 0) {
            float d = __ldg(&fc1_b[unit]);
            #pragma unroll
            for (int k = 0; k < H_; ++k)
                d = fmaf(hfin[k], __ldg(&fc1_w[unit * H_ + k]), d);
            d = fmaxf(d, 0.f);
            s_g[e][unit] = d * __ldg(&fc2_w[unit]);
        }
        __syncthreads();
        if (g == 0) {
            float p = __ldg(&fc2_b[0]);
            #pragma unroll
            for (int k = 0; k < H_; ++k) p += s_g[e][k];
            out_final[elem] = p;
        }
    }
}

extern "C" void kernel_launch(void* const* d_in, const int* in_sizes, int n_in,
                              void* d_out, int out_size) {
    const float* x     = (const float*)d_in[0];
    const float* Wih0  = (const float*)d_in[1];
    const float* Whh0  = (const float*)d_in[2];
    const float* bih0  = (const float*)d_in[3];
    const float* bhh0  = (const float*)d_in[4];
    const float* Wih1  = (const float*)d_in[5];
    const float* Whh1  = (const float*)d_in[6];
    const float* bih1  = (const float*)d_in[7];
    const float* bhh1  = (const float*)d_in[8];
    const float* Wih2  = (const float*)d_in[9];
    const float* Whh2  = (const float*)d_in[10];
    const float* bih2  = (const float*)d_in[11];
    const float* bhh2  = (const float*)d_in[12];
    const float* fc1w  = (const float*)d_in[13];
    const float* fc1b  = (const float*)d_in[14];
    const float* fc2w  = (const float*)d_in[15];
    const float* fc2b  = (const float*)d_in[16];
    float* out = (float*)d_out;

    dim3 block(EPB * G_);          // 320
    dim3 grid(B_ / EPB);           // 2048

    lstm_fused<F_, 0, 0><<<grid, block>>>(
        x, Wih0, Whh0, bih0, bhh0, nullptr, nullptr, nullptr, nullptr, nullptr);
    lstm_fused<H_, 1, 1><<<grid, block>>>(
        nullptr, Wih1, Whh1, bih1, bhh1, nullptr, nullptr, nullptr, nullptr, nullptr);
    lstm_fused<H_, 2, 2><<<grid, block>>>(
        nullptr, Wih2, Whh2, bih2, bhh2, fc1w, fc1b, fc2w, fc2b, out);
}

// round 4
// speedup vs baseline: 2.0519x; 1.3728x over previous
#include <cuda_runtime.h>

// Problem constants
#define B_  8192
#define T_  336
#define F_  8
#define H_  20
#define G_  80           // 4*H gate rows
#define PPB 4            // element-pairs per block -> 8 elements / block
#define NPAIR (B_ / 2)   // 4096

typedef unsigned long long u64;

// Inter-layer hidden sequences, pair-interleaved: g_buf[pair][t][unit] = {h_e0, h_e1}
__device__ u64 g_buf0[(size_t)NPAIR * T_ * H_];
__device__ u64 g_buf1[(size_t)NPAIR * T_ * H_];

// ---- packed f32x2 helpers (sm_103a) ----
__device__ __forceinline__ u64 pk(float lo, float hi) {
    u64 r; asm("mov.b64 %0, {%1, %2};" : "=l"(r) : "f"(lo), "f"(hi)); return r;
}
__device__ __forceinline__ float2 upk(u64 v) {
    float2 f; asm("mov.b64 {%0, %1}, %2;" : "=f"(f.x), "=f"(f.y) : "l"(v)); return f;
}
__device__ __forceinline__ u64 ffma2(u64 a, u64 b, u64 c) {
    u64 d; asm("fma.rn.f32x2 %0, %1, %2, %3;" : "=l"(d) : "l"(a), "l"(b), "l"(c)); return d;
}
__device__ __forceinline__ u64 fmul2(u64 a, u64 b) {
    u64 d; asm("mul.rn.f32x2 %0, %1, %2;" : "=l"(d) : "l"(a), "l"(b)); return d;
}
__device__ __forceinline__ u64 fadd2(u64 a, u64 b) {
    u64 d; asm("add.rn.f32x2 %0, %1, %2;" : "=l"(d) : "l"(a), "l"(b)); return d;
}

__device__ __forceinline__ float sig1(float x) {           // sigmoid, exact-ish
    return __fdividef(1.f, 1.f + __expf(-x));
}

// SRC: 0 = param in_seq (float [B,T,IN]), 1 = g_buf0, 2 = g_buf1 (pair-interleaved u64)
// DST: 0 = g_buf0, 1 = g_buf1, 2 = final (FC head -> out_final)
template <int IN, int SRC, int DST>
__global__ __launch_bounds__(PPB * G_)
void lstm_fused(
    const float* __restrict__ in_seq,
    const float* __restrict__ W_ih,   // [80, IN]
    const float* __restrict__ W_hh,   // [80, 20]
    const float* __restrict__ b_ih,   // [80]
    const float* __restrict__ b_hh,   // [80]
    const float* __restrict__ fc1_w,  // [20, 20]
    const float* __restrict__ fc1_b,  // [20]
    const float* __restrict__ fc2_w,  // [20]
    const float* __restrict__ fc2_b,  // [1]
    float* __restrict__ out_final)    // [B]
{
    constexpr int KTOT = IN + H_;        // 28 or 40 (even)
    constexpr int K2   = KTOT / 2;       // ulonglong2 slots
    constexpr bool FINAL = (DST == 2);

    // [x_t | h] packed pairs, double buffered. u64 slot k = {val_e0[k], val_e1[k]}.
    __shared__ ulonglong2 s_hx[2][PPB][K2];
    // Activated gates, packed pairs.
    __shared__ u64 s_g[PPB][G_];

    const int tid  = threadIdx.x;
    const int e    = tid / G_;           // local pair 0..3
    const int g    = tid % G_;           // gate row 0..79
    const int unit = g % H_;
    const int type = g / H_;             // 0=i 1=f 2=g 3=o
    const size_t pair = (size_t)blockIdx.x * PPB + e;

    // ---- weights dup-packed to registers ----
    u64 w2[KTOT];
    #pragma unroll
    for (int k = 0; k < IN; ++k) { float w = __ldg(&W_ih[g * IN + k]); w2[k] = pk(w, w); }
    #pragma unroll
    for (int k = 0; k < H_; ++k) { float w = __ldg(&W_hh[g * H_ + k]); w2[IN + k] = pk(w, w); }
    const float bb = __ldg(&b_ih[g]) + __ldg(&b_hh[g]);
    const u64 bias2 = pk(bb, bb);
    // activation selectors: pre-scale and post fma(am, y, bm)
    const float sc = (type == 2) ? -2.f : -1.f;
    const float am = (type == 2) ?  2.f :  1.f;
    const float bm = (type == 2) ? -1.f :  0.f;

    const u64* __restrict__ srcb = (SRC == 1) ? g_buf0 : g_buf1;   // layers 1/2
    u64* __restrict__ dstb = (DST == 0) ? g_buf0 : g_buf1;

    const u64* __restrict__ inp_u = srcb + pair * T_ * H_;         // SRC != 0
    const float* __restrict__ inp_f0 = in_seq + (size_t)(2 * pair)     * T_ * IN;
    const float* __restrict__ inp_f1 = in_seq + (size_t)(2 * pair + 1) * T_ * IN;
    u64* __restrict__ outp = FINAL ? nullptr : dstb + pair * T_ * H_;

    // ---- prologue: stage x0 into buf0, zero h slots, prefetch x1 ----
    u64   xr_u = 0;   // layers 1/2 prefetch
    float xr_f = 0.f; // layer 0 prefetch
    const int kx = g >> 1, elx = g & 1;   // layer-0 staging mapping

    {
        float* f0 = (float*)&s_hx[0][e][0];
        if (SRC == 0) {
            if (g < 2 * IN) {
                const float* ip = elx ? inp_f1 : inp_f0;
                f0[2 * kx + elx] = ip[kx];               // x0
                xr_f = ip[IN + kx];                      // x1
            }
        } else {
            if (g < H_) {
                ((u64*)f0)[g] = inp_u[g];                // x0 (pair-packed)
                xr_u = inp_u[H_ + g];                    // x1
            }
        }
        if (g >= 20 && g < 20 + H_)
            ((u64*)f0)[IN + (g - 20)] = 0ULL;            // h = 0
    }
    __syncthreads();

    u64 c2 = 0ULL;     // packed cell state (owner threads, type==0)
    int cur = 0;

    for (int t = 0; t < T_; ++t) {
        // stage prefetched x[t+1] into next buffer; prefetch x[t+2]
        float* fn = (float*)&s_hx[cur ^ 1][e][0];
        if (SRC == 0) {
            if (g < 2 * IN) {
                if (t + 1 < T_) fn[2 * kx + elx] = xr_f;
                if (t + 2 < T_) {
                    const float* ip = elx ? inp_f1 : inp_f0;
                    xr_f = ip[(size_t)(t + 2) * IN + kx];
                }
            }
        } else {
            if (g < H_) {
                if (t + 1 < T_) ((u64*)fn)[g] = xr_u;
                if (t + 2 < T_) xr_u = inp_u[(size_t)(t + 2) * H_ + g];
            }
        }

        // ---- gate pre-activation: K2 LDS.128 + KTOT FFMA2, two chains ----
        const ulonglong2* hx = &s_hx[cur][e][0];
        u64 acc0 = bias2, acc1 = pk(0.f, 0.f);
        #pragma unroll
        for (int q = 0; q < K2; ++q) {
            ulonglong2 v = hx[q];
            acc0 = ffma2(v.x, w2[2 * q],     acc0);
            acc1 = ffma2(v.y, w2[2 * q + 1], acc1);
        }
        float2 a = upk(fadd2(acc0, acc1));

        // activation (sigmoid / tanh via exp, exact path)
        float y0 = __fdividef(1.f, 1.f + __expf(sc * a.x));
        float y1 = __fdividef(1.f, 1.f + __expf(sc * a.y));
        s_g[e][g] = pk(fmaf(am, y0, bm), fmaf(am, y1, bm));

        __syncthreads();   // gates visible

        if (type == 0) {
            u64 ig = s_g[e][unit];
            u64 fg = s_g[e][unit + 20];
            u64 gg = s_g[e][unit + 40];
            u64 og = s_g[e][unit + 60];
            c2 = ffma2(fg, c2, fmul2(ig, gg));
            float2 cf = upk(c2);
            float t0 = fmaf(2.f, sig1(2.f * cf.x), -1.f);
            float t1 = fmaf(2.f, sig1(2.f * cf.y), -1.f);
            u64 h2 = fmul2(og, pk(t0, t1));
            ((u64*)fn)[IN + unit] = h2;                      // h into next buffer
            if (!FINAL) outp[(size_t)t * H_ + unit] = h2;    // pair-packed STG.64
        }

        __syncthreads();   // h + staged x visible
        cur ^= 1;
    }

    if (FINAL) {
        const u64* hfin = (const u64*)&s_hx[cur][e][0] + IN;  // final h pairs
        if (type == 0) {
            float b1 = __ldg(&fc1_b[unit]);
            u64 d2 = pk(b1, b1);
            #pragma unroll
            for (int k = 0; k < H_; ++k) {
                float w = __ldg(&fc1_w[unit * H_ + k]);
                d2 = ffma2(hfin[k], pk(w, w), d2);
            }
            float2 df = upk(d2);
            float w2o = __ldg(&fc2_w[unit]);
            s_g[e][unit] = pk(fmaxf(df.x, 0.f) * w2o, fmaxf(df.y, 0.f) * w2o);
        }
        __syncthreads();
        if (g == 0) {
            float p0 = __ldg(&fc2_b[0]), p1 = p0;
            #pragma unroll
            for (int k = 0; k < H_; ++k) {
                float2 v = upk(s_g[e][k]);
                p0 += v.x; p1 += v.y;
            }
            float2* o2 = (float2*)&out_final[2 * pair];
            *o2 = make_float2(p0, p1);
        }
    }
}

extern "C" void kernel_launch(void* const* d_in, const int* in_sizes, int n_in,
                              void* d_out, int out_size) {
    const float* x     = (const float*)d_in[0];
    const float* Wih0  = (const float*)d_in[1];
    const float* Whh0  = (const float*)d_in[2];
    const float* bih0  = (const float*)d_in[3];
    const float* bhh0  = (const float*)d_in[4];
    const float* Wih1  = (const float*)d_in[5];
    const float* Whh1  = (const float*)d_in[6];
    const float* bih1  = (const float*)d_in[7];
    const float* bhh1  = (const float*)d_in[8];
    const float* Wih2  = (const float*)d_in[9];
    const float* Whh2  = (const float*)d_in[10];
    const float* bih2  = (const float*)d_in[11];
    const float* bhh2  = (const float*)d_in[12];
    const float* fc1w  = (const float*)d_in[13];
    const float* fc1b  = (const float*)d_in[14];
    const float* fc2w  = (const float*)d_in[15];
    const float* fc2b  = (const float*)d_in[16];
    float* out = (float*)d_out;

    dim3 block(PPB * G_);            // 320
    dim3 grid(NPAIR / PPB);          // 1024

    lstm_fused<F_, 0, 0><<<grid, block>>>(
        x, Wih0, Whh0, bih0, bhh0, nullptr, nullptr, nullptr, nullptr, nullptr);
    lstm_fused<H_, 1, 1><<<grid, block>>>(
        nullptr, Wih1, Whh1, bih1, bhh1, nullptr, nullptr, nullptr, nullptr, nullptr);
    lstm_fused<H_, 2, 2><<<grid, block>>>(
        nullptr, Wih2, Whh2, bih2, bhh2, fc1w, fc1b, fc2w, fc2b, out);
}